// round 7
// baseline (speedup 1.0000x reference)
#include <cuda_runtime.h>
#include <cstddef>

#define B_    256
#define T_    500
#define NIN_  128
#define NH_   512
#define NO_   64

#define REC_SMEM (NH_*32*4 + 8*32*36*4)   // hs[512][32] + part[8][32][36] = 102400 B

// ---------------------------------------------------------------------------
// Device scratch (no runtime allocation allowed)
// ---------------------------------------------------------------------------
__device__ __align__(16) float    g_h[2 * NH_ * B_];   // ping-pong hidden, k-major [k][b]
__device__ __align__(16) float    g_bias[NH_];         // b_ih + b_hh
__device__ unsigned g_barr[8 * 32];                    // per-batch-group barrier counters

// ---------------------------------------------------------------------------
// f32x2 packed FMA helpers
// ---------------------------------------------------------------------------
__device__ __forceinline__ unsigned long long pack2(float lo, float hi) {
    unsigned long long r;
    asm("mov.b64 %0, {%1, %2};" : "=l"(r) : "f"(lo), "f"(hi));
    return r;
}
__device__ __forceinline__ void fma2(unsigned long long& d,
                                     unsigned long long a, unsigned long long b) {
    asm("fma.rn.f32x2 %0, %1, %2, %0;" : "+l"(d) : "l"(a), "l"(b));
}
__device__ __forceinline__ float2 unpack2(unsigned long long v) {
    float2 f;
    asm("mov.b64 {%0, %1}, %2;" : "=f"(f.x), "=f"(f.y) : "l"(v));
    return f;
}

union U4 { float4 v; unsigned long long p[2]; };

// ---------------------------------------------------------------------------
// Init: transpose h0 into g_h slot 0 (k-major), fold biases, reset barriers.
// <<<NH_, B_>>>
// ---------------------------------------------------------------------------
__global__ void init_kernel(const float* __restrict__ h0,
                            const float* __restrict__ b_ih,
                            const float* __restrict__ b_hh) {
    int k = blockIdx.x;
    int b = threadIdx.x;
    g_h[(size_t)k * B_ + b] = h0[(size_t)b * NH_ + k];
    if (b == 0) g_bias[k] = b_ih[k] + b_hh[k];
    if (k == 0 && b < 8) g_barr[b * 32] = 0u;
}

// ---------------------------------------------------------------------------
// C[m][c] = sum_k A[m][k]*Bm[c][k] + bias[c]
// 128x64 tile, K-chunks of 32, 8x4 micro-tile per thread, f32x2 FMAs.
// bias_mode: 1 -> g_bias, 0 -> bias pointer.   grid(M/128, Ntot/64), 256 thr.
// ---------------------------------------------------------------------------
__global__ __launch_bounds__(256)
void gemm_bias_kernel(const float* __restrict__ A, const float* __restrict__ Bm,
                      const float* __restrict__ bias, float* __restrict__ C,
                      int K, int Ntot, int bias_mode) {
    __shared__ float xs[32][128];   // k-major A tile
    __shared__ float ws[32][64];    // k-major B tile

    const int tid = threadIdx.x;
    const int m0  = blockIdx.x * 128;
    const int c0  = blockIdx.y * 64;
    const int tx  = tid & 15;       // col quad (4 cols)
    const int ty  = tid >> 4;       // row octet (8 rows)

    const int arow = tid & 127, akq = tid >> 7;
    const int bcol = tid & 63,  bkh = tid >> 6;

    unsigned long long acc[16];
#pragma unroll
    for (int i = 0; i < 16; i++) acc[i] = 0ull;

    for (int kc = 0; kc < K; kc += 32) {
#pragma unroll
        for (int i = 0; i < 4; i++) {
            int kk = akq * 16 + i * 4;
            float4 v = *(const float4*)(A + (size_t)(m0 + arow) * K + kc + kk);
            xs[kk + 0][arow] = v.x; xs[kk + 1][arow] = v.y;
            xs[kk + 2][arow] = v.z; xs[kk + 3][arow] = v.w;
        }
#pragma unroll
        for (int i = 0; i < 2; i++) {
            int kk = bkh * 8 + i * 4;
            float4 v = *(const float4*)(Bm + (size_t)(c0 + bcol) * K + kc + kk);
            ws[kk + 0][bcol] = v.x; ws[kk + 1][bcol] = v.y;
            ws[kk + 2][bcol] = v.z; ws[kk + 3][bcol] = v.w;
        }
        __syncthreads();

#pragma unroll
        for (int kk = 0; kk < 32; kk++) {
            U4 a0, a1, b4;
            a0.v = *(const float4*)(&xs[kk][8 * ty]);
            a1.v = *(const float4*)(&xs[kk][8 * ty + 4]);
            b4.v = *(const float4*)(&ws[kk][4 * tx]);
            unsigned long long s0 = pack2(b4.v.x, b4.v.x);
            unsigned long long s1 = pack2(b4.v.y, b4.v.y);
            unsigned long long s2 = pack2(b4.v.z, b4.v.z);
            unsigned long long s3 = pack2(b4.v.w, b4.v.w);
            fma2(acc[0],  a0.p[0], s0); fma2(acc[1],  a0.p[1], s0);
            fma2(acc[2],  a1.p[0], s0); fma2(acc[3],  a1.p[1], s0);
            fma2(acc[4],  a0.p[0], s1); fma2(acc[5],  a0.p[1], s1);
            fma2(acc[6],  a1.p[0], s1); fma2(acc[7],  a1.p[1], s1);
            fma2(acc[8],  a0.p[0], s2); fma2(acc[9],  a0.p[1], s2);
            fma2(acc[10], a1.p[0], s2); fma2(acc[11], a1.p[1], s2);
            fma2(acc[12], a0.p[0], s3); fma2(acc[13], a0.p[1], s3);
            fma2(acc[14], a1.p[0], s3); fma2(acc[15], a1.p[1], s3);
        }
        __syncthreads();
    }

    const float* bp = bias_mode ? g_bias : bias;
    float4 bv = *(const float4*)(bp + c0 + 4 * tx);

#pragma unroll
    for (int i = 0; i < 4; i++) {
        float2 p0 = unpack2(acc[0 * 4 + i]);
        float2 p1 = unpack2(acc[1 * 4 + i]);
        float2 p2 = unpack2(acc[2 * 4 + i]);
        float2 p3 = unpack2(acc[3 * 4 + i]);
        float4 lo = make_float4(p0.x + bv.x, p1.x + bv.y, p2.x + bv.z, p3.x + bv.w);
        float4 hi = make_float4(p0.y + bv.x, p1.y + bv.y, p2.y + bv.z, p3.y + bv.w);
        size_t r0 = (size_t)(m0 + 8 * ty + 2 * i) * Ntot + c0 + 4 * tx;
        *(float4*)(C + r0)        = lo;
        *(float4*)(C + r0 + Ntot) = hi;
    }
}

// ---------------------------------------------------------------------------
// Per-batch-group software barrier (16 CTAs share one monotonic counter).
// ---------------------------------------------------------------------------
__device__ __forceinline__ void gb_barrier(int gb, unsigned target) {
    __syncthreads();
    if (threadIdx.x == 0) {
        __threadfence();
        atomicAdd(&g_barr[gb * 32], 1u);
        volatile unsigned* p = &g_barr[gb * 32];
        while (*p < target) {}
        __threadfence();
    }
    __syncthreads();
}

// ---------------------------------------------------------------------------
// Persistent recurrence. 128 CTAs x 256 threads. CTA(gb,cg): 32 rows x 32 cols.
// W_hh slice in registers per thread; h tile k-major in smem (broadcast LDS).
// ---------------------------------------------------------------------------
__global__ __launch_bounds__(256, 1)
void rnn_rec_kernel(const float* __restrict__ W_hh, const float* __restrict__ alpha,
                    float* __restrict__ outH, float* __restrict__ outF) {
    extern __shared__ float sm[];
    float* hs   = sm;                 // [512][32]
    float* part = sm + NH_ * 32;      // [8][32][36]

    const int tid = threadIdx.x;
    const int gb  = blockIdx.x & 7;    // batch group
    const int cg  = blockIdx.x >> 3;   // col group

    // compute role: thread (c,g) owns W_hh[cg*32+c][g*64 .. g*64+63]
    const int c = tid & 31, g = tid >> 5;
    const int cglob = cg * 32 + c;
    float w[64];
#pragma unroll
    for (int i = 0; i < 16; i++) {
        float4 v = *(const float4*)(W_hh + (size_t)cglob * NH_ + g * 64 + 4 * i);
        w[4 * i] = v.x; w[4 * i + 1] = v.y; w[4 * i + 2] = v.z; w[4 * i + 3] = v.w;
    }

    // reduction role
    const int rb = tid >> 3;          // batch row 0..31
    const int cq = tid & 7;           // col quad
    float4 av = *(const float4*)(alpha + cg * 32 + 4 * cq);
    const float al0 = av.x, al1 = av.y, al2 = av.z, al3 = av.w;
    const float om0 = 1.f - av.x, om1 = 1.f - av.y, om2 = 1.f - av.z, om3 = 1.f - av.w;

    // h-tile loader role
    const int lc4 = tid & 7, lkb = tid >> 3;

    for (int t = 0; t < T_; t++) {
        // 1) load h_t tile (k-major global -> k-major smem), L2 path
        const float* hsrc = g_h + (size_t)(t & 1) * NH_ * B_;
#pragma unroll
        for (int i = 0; i < 16; i++) {
            int k = lkb + 32 * i;
            float4 v = __ldcg((const float4*)(hsrc + (size_t)k * B_ + gb * 32 + 4 * lc4));
            *(float4*)(hs + k * 32 + 4 * lc4) = v;
        }
        __syncthreads();

        // 2) partial GEMM over this thread's 64-k slice, 32 batch rows
        unsigned long long acc[16];
#pragma unroll
        for (int i = 0; i < 16; i++) acc[i] = 0ull;
        const float* hbase = hs + g * 64 * 32;
#pragma unroll
        for (int kk = 0; kk < 64; kk++) {
            unsigned long long wsp = pack2(w[kk], w[kk]);
            const float* row = hbase + kk * 32;
#pragma unroll
            for (int q = 0; q < 8; q++) {
                U4 hv;
                hv.v = *(const float4*)(row + 4 * q);    // broadcast
                fma2(acc[2 * q],     hv.p[0], wsp);
                fma2(acc[2 * q + 1], hv.p[1], wsp);
            }
        }
#pragma unroll
        for (int q = 0; q < 8; q++) {
            float2 lo = unpack2(acc[2 * q]);
            float2 hi = unpack2(acc[2 * q + 1]);
            float4 v = make_float4(lo.x, lo.y, hi.x, hi.y);
            *(float4*)(part + (size_t)(g * 32 + c) * 36 + 4 * q) = v;
        }
        __syncthreads();

        // 3) reduce k-groups, add pre (in place in outH), relu, leaky update
        float s0 = 0.f, s1 = 0.f, s2 = 0.f, s3 = 0.f;
        const int cl = 4 * cq;
#pragma unroll
        for (int gg = 0; gg < 8; gg++) {
            const float* pb = part + (size_t)(gg * 32 + cl) * 36 + rb;
            s0 += pb[0];
            s1 += pb[36];
            s2 += pb[72];
            s3 += pb[108];
        }
        size_t haddr = ((size_t)(gb * 32 + rb) * T_ + t) * NH_ + cg * 32 + 4 * cq;
        float4 pre = *(const float4*)(outH + haddr);
        float c0v = s0 + pre.x, c1v = s1 + pre.y, c2v = s2 + pre.z, c3v = s3 + pre.w;
        c0v = c0v > 0.f ? c0v : 0.f;
        c1v = c1v > 0.f ? c1v : 0.f;
        c2v = c2v > 0.f ? c2v : 0.f;
        c3v = c3v > 0.f ? c3v : 0.f;
        const int kcol = cg * 32 + 4 * cq;
        float h0v = om0 * hs[(size_t)(kcol + 0) * 32 + rb] + al0 * c0v;
        float h1v = om1 * hs[(size_t)(kcol + 1) * 32 + rb] + al1 * c1v;
        float h2v = om2 * hs[(size_t)(kcol + 2) * 32 + rb] + al2 * c2v;
        float h3v = om3 * hs[(size_t)(kcol + 3) * 32 + rb] + al3 * c3v;
        float4 hn4 = make_float4(h0v, h1v, h2v, h3v);
        *(float4*)(outH + haddr) = hn4;                       // hidden_list

        if (t != T_ - 1) {
            float* hdst = g_h + (size_t)((t + 1) & 1) * NH_ * B_;
            __stcg(hdst + (size_t)(kcol + 0) * B_ + gb * 32 + rb, h0v);
            __stcg(hdst + (size_t)(kcol + 1) * B_ + gb * 32 + rb, h1v);
            __stcg(hdst + (size_t)(kcol + 2) * B_ + gb * 32 + rb, h2v);
            __stcg(hdst + (size_t)(kcol + 3) * B_ + gb * 32 + rb, h3v);
            gb_barrier(gb, (unsigned)(t + 1) * 16u);
        } else {
            *(float4*)(outF + (size_t)(gb * 32 + rb) * NH_ + kcol) = hn4;
        }
    }
}

// ---------------------------------------------------------------------------
extern "C" void kernel_launch(void* const* d_in, const int* in_sizes, int n_in,
                              void* d_out, int out_size) {
    const float* x     = (const float*)d_in[0];   // [B,T,128]
    const float* h0    = (const float*)d_in[1];   // [B,512]
    const float* Wih   = (const float*)d_in[2];   // [512,128]
    const float* Whh   = (const float*)d_in[3];   // [512,512]
    const float* bih   = (const float*)d_in[4];   // [512]
    const float* bhh   = (const float*)d_in[5];   // [512]
    const float* Wout  = (const float*)d_in[6];   // [64,512]
    const float* bout  = (const float*)d_in[7];   // [64]
    const float* alpha = (const float*)d_in[8];   // [512]

    float* out  = (float*)d_out;
    float* outH = out;                                   // hidden_list [B,T,512]
    float* outO = out + (size_t)B_ * T_ * NH_;           // output_list [B,T,64]
    float* outF = outO + (size_t)B_ * T_ * NO_;          // h_final     [B,512]

    cudaFuncSetAttribute(rnn_rec_kernel,
                         cudaFuncAttributeMaxDynamicSharedMemorySize, REC_SMEM);

    // 1) init hidden transpose + bias fold + barrier reset
    init_kernel<<<NH_, B_>>>(h0, bih, bhh);

    // 2) pre = x @ W_ih^T + (b_ih + b_hh), into hidden_list region (in-place)
    gemm_bias_kernel<<<dim3((B_ * T_) / 128, NH_ / 64), 256>>>(
        x, Wih, nullptr, outH, NIN_, NH_, 1);

    // 3) 500-step recurrence, persistent kernel, overwrites pre with h_t
    rnn_rec_kernel<<<128, 256, REC_SMEM>>>(Whh, alpha, outH, outF);

    // 4) output_list = hidden_list @ W_out^T + b_out
    gemm_bias_kernel<<<dim3((B_ * T_) / 128, NO_ / 64), 256>>>(
        outH, Wout, bout, outO, NH_, NO_, 0);
}